// round 1
// baseline (speedup 1.0000x reference)
#include <cuda_runtime.h>
#include <cuda_bf16.h>

// LeakyAvg: out[b,h,t,d] = sum_{s<=t} exp(-beta_h*(t-s)) * k[b,h,s,d]
// = linear recurrence y[t] = w*y[t-1] + k[t], w = exp(-beta_h), beta_h in [0.5, 5].
// w^64 <= e^{-32} ~ 1.6e-14 << fp32 eps, so a 64-step warm-up from zero state
// reproduces the exact scan state at any chunk boundary to fp32 precision.
//
// Layout: one warp per (b*NH+h, t-chunk). 32 lanes x float2 = 64 = HS head dims,
// giving one coalesced 256B load + 256B store per warp per timestep.

#define BB 4
#define NH 16
#define TT 2048
#define HS 64
#define CHUNK 64   // outputs per warp
#define WARM 64    // warm-up window (exact to fp32 for beta >= 0.5)
#define EXP_SCALING 10.0f

#define NCHUNKS (TT / CHUNK)
#define NWARPS (BB * NH * NCHUNKS)

__global__ void __launch_bounds__(256) leaky_avg_kernel(
    const float* __restrict__ k,
    const float* __restrict__ beta_param,
    float* __restrict__ out)
{
    const int warp = (blockIdx.x * blockDim.x + threadIdx.x) >> 5;
    const int lane = threadIdx.x & 31;
    if (warp >= NWARPS) return;

    const int chunk = warp & (NCHUNKS - 1);
    const int bh    = warp / NCHUNKS;
    const int h     = bh & (NH - 1);

    const float beta = fabsf(beta_param[h]) * EXP_SCALING;
    const float w    = expf(-beta);

    const int t0 = chunk * CHUNK;
    const int tw = (t0 >= WARM) ? (t0 - WARM) : 0;

    // base pointer for this (b,h) row, at this lane's 2 head-dim columns
    const size_t row = (size_t)bh * TT * HS + (size_t)lane * 2;
    const float* __restrict__ kp = k + row;
    float*       __restrict__ op = out + row;

    float y0 = 0.0f, y1 = 0.0f;

    // Warm-up: run the recurrence over the halo without writing.
    // (chunk 0: loop is empty -> exact zero initial state)
    #pragma unroll 8
    for (int t = tw; t < t0; ++t) {
        float2 v = *reinterpret_cast<const float2*>(kp + (size_t)t * HS);
        y0 = fmaf(w, y0, v.x);
        y1 = fmaf(w, y1, v.y);
    }

    // Body: recurrence + store.
    #pragma unroll 8
    for (int t = t0; t < t0 + CHUNK; ++t) {
        float2 v = *reinterpret_cast<const float2*>(kp + (size_t)t * HS);
        y0 = fmaf(w, y0, v.x);
        y1 = fmaf(w, y1, v.y);
        float2 r; r.x = y0; r.y = y1;
        *reinterpret_cast<float2*>(op + (size_t)t * HS) = r;
    }
}

extern "C" void kernel_launch(void* const* d_in, const int* in_sizes, int n_in,
                              void* d_out, int out_size)
{
    const float* k    = (const float*)d_in[0];        // (B, NH, T, HS) f32
    const float* beta = (const float*)d_in[1];        // (1, NH, 1, 1) f32
    float*       out  = (float*)d_out;                // (B, NH, T, HS) f32

    const int threads = 256;
    const int totalThreads = NWARPS * 32;             // 2048 warps
    const int blocks = (totalThreads + threads - 1) / threads;
    leaky_avg_kernel<<<blocks, threads>>>(k, beta, out);
}

// round 2
// speedup vs baseline: 1.1425x; 1.1425x over previous
#include <cuda_runtime.h>
#include <cuda_bf16.h>

// LeakyAvg: out[b,h,t,d] = sum_{s<=t} exp(-beta_h*(t-s)) * k[b,h,s,d]
// = linear recurrence y[t] = w*y[t-1] + k[t], w = exp(-beta_h), beta_h in [0.5, 5].
// w^48 <= e^{-24} ~ 4e-11, so a 48-step warm-up from zero state reproduces the
// scan state at any chunk boundary to far below the 1e-3 tolerance (and below
// fp32 eps for all but the smallest beta).
//
// R2: maximize concurrency (R1 was latency-starved: occ 19.5%, DRAM 22%).
//   - one warp per (b*NH+h, half-of-HS, t-chunk); lane owns 1 fp32 column
//     -> 128B coalesced load/store per warp per timestep
//   - CHUNK=32, WARM=48 -> 8192 warps (~55/SM). Halo re-reads are L2 hits
//     (33MB input << L2), DRAM stays at compulsory 67MB.

#define BB 4
#define NH 16
#define TT 2048
#define HS 64
#define CHUNK 32
#define WARM 48
#define EXP_SCALING 10.0f

#define NCHUNKS (TT / CHUNK)              // 64
#define NHALF   2                          // HS split across 2 warps
#define NWARPS  (BB * NH * NHALF * NCHUNKS)  // 8192

__global__ void __launch_bounds__(256) leaky_avg_kernel(
    const float* __restrict__ k,
    const float* __restrict__ beta_param,
    float* __restrict__ out)
{
    const int warp = (blockIdx.x * blockDim.x + threadIdx.x) >> 5;
    const int lane = threadIdx.x & 31;
    if (warp >= NWARPS) return;

    const int chunk = warp & (NCHUNKS - 1);
    const int rest  = warp >> 6;             // / NCHUNKS
    const int half  = rest & (NHALF - 1);
    const int bh    = rest >> 1;
    const int h     = bh & (NH - 1);

    const float beta = fabsf(beta_param[h]) * EXP_SCALING;
    const float w    = expf(-beta);

    const int t0 = chunk * CHUNK;
    const int tw = (t0 >= WARM) ? (t0 - WARM) : 0;

    // base pointer for this (b,h) row at this lane's column
    const size_t col = (size_t)half * 32 + lane;
    const size_t row = (size_t)bh * TT * HS + col;
    const float* __restrict__ kp = k + row;
    float*       __restrict__ op = out + row;

    float y = 0.0f;

    // Warm-up over the halo (no writes). chunk 0: empty -> exact zero state.
    #pragma unroll 8
    for (int t = tw; t < t0; ++t) {
        y = fmaf(w, y, kp[(size_t)t * HS]);
    }

    // Body: recurrence + store.
    #pragma unroll 8
    for (int t = t0; t < t0 + CHUNK; ++t) {
        y = fmaf(w, y, kp[(size_t)t * HS]);
        op[(size_t)t * HS] = y;
    }
}

extern "C" void kernel_launch(void* const* d_in, const int* in_sizes, int n_in,
                              void* d_out, int out_size)
{
    const float* k    = (const float*)d_in[0];   // (B, NH, T, HS) f32
    const float* beta = (const float*)d_in[1];   // (1, NH, 1, 1) f32
    float*       out  = (float*)d_out;           // (B, NH, T, HS) f32

    const int threads = 256;
    const int totalThreads = NWARPS * 32;        // 8192 warps
    const int blocks = totalThreads / threads;   // 1024
    leaky_avg_kernel<<<blocks, threads>>>(k, beta, out);
}

// round 3
// speedup vs baseline: 1.1693x; 1.0234x over previous
#include <cuda_runtime.h>
#include <cuda_bf16.h>

// LeakyAvg: out[b,h,t,d] = sum_{s<=t} exp(-beta_h*(t-s)) * k[b,h,s,d]
// = recurrence y[t] = w*y[t-1] + k[t], w = exp(-beta_h), beta_h in [0.5, 5].
//
// R3: block-level chunked scan.
//  - Block = 10 warps: 2 warm chunks + 8 body chunks of 16 timesteps (TILE=128).
//  - Lane owns 2 head-dims (float2); warp load/store = 256B coalesced.
//  - Phase 1: all 16 loads issued up-front into regs (max MLP), local scan in place.
//  - Phase 2: carry via smem: C_j = S_{j-1} + w^16 * C_{j-2 chain}, <=9 fma steps.
//  - Phase 3: out[u] = y_loc[u] + C * w^(u+1), geometric correction, store.
//  32-step warm-up => truncation <= e^{-16} ~ 1.1e-7 relative (beta >= 0.5).

#define BB 4
#define NH 16
#define TT 2048
#define HS 64
#define EXP_SCALING 10.0f

#define CH 16                 // timesteps per warp-chunk
#define NBODY 8               // body chunks per block
#define NWARM 2               // warm chunks per block (32-step warm-up)
#define NWARPB (NBODY + NWARM)        // 10 warps
#define THREADS (NWARPB * 32)          // 320
#define TILE (NBODY * CH)              // 128 timesteps per block
#define NTILES (TT / TILE)             // 16
#define NROWS (BB * NH)                // 64

__global__ void __launch_bounds__(THREADS) leaky_avg_kernel(
    const float* __restrict__ k,
    const float* __restrict__ beta_param,
    float* __restrict__ out)
{
    const int lane = threadIdx.x & 31;
    const int j    = threadIdx.x >> 5;            // warp index in block (0..9)
    const int row  = blockIdx.x >> 4;             // bh index (0..63)
    const int tile = blockIdx.x & (NTILES - 1);   // 0..15
    const int h    = row & (NH - 1);

    const float beta = fabsf(beta_param[h]) * EXP_SCALING;
    const float w    = expf(-beta);
    const float w2 = w * w, w4 = w2 * w2, w8 = w4 * w4;
    const float w16 = w8 * w8;                    // per-chunk decay

    // chunk start: warm chunks (j=0,1) sit at [tile0-32, tile0)
    const int chunk_start = tile * TILE + (j - NWARM) * CH;

    // float2 view of this (b,h) row at this lane's 2 columns; stride 32 float2/t
    const float2* __restrict__ kp =
        reinterpret_cast<const float2*>(k + (size_t)row * TT * HS) + lane;

    // ---- Phase 1: front-batched loads, then in-place local scan ----
    float2 v[CH];
    #pragma unroll
    for (int u = 0; u < CH; ++u) {
        const int t = chunk_start + u;
        if (t >= 0) v[u] = kp[(size_t)t * (HS / 2)];
        else        v[u] = make_float2(0.0f, 0.0f);
    }

    float2 y = make_float2(0.0f, 0.0f);
    #pragma unroll
    for (int u = 0; u < CH; ++u) {
        y.x = fmaf(w, y.x, v[u].x);
        y.y = fmaf(w, y.y, v[u].y);
        v[u] = y;                                  // local inclusive scan
    }

    __shared__ float2 sS[NWARPB * 32];
    sS[j * 32 + lane] = y;                         // chunk-final state
    __syncthreads();

    // ---- Phase 2+3: body warps fold carry and store corrected outputs ----
    if (j >= NWARM) {
        float2 C = make_float2(0.0f, 0.0f);
        for (int i = 0; i < j; ++i) {              // C = sum_i S_i * w16^(j-1-i)
            const float2 s = sS[i * 32 + lane];
            C.x = fmaf(C.x, w16, s.x);
            C.y = fmaf(C.y, w16, s.y);
        }

        float2* __restrict__ op =
            reinterpret_cast<float2*>(out + (size_t)row * TT * HS) + lane;

        float px = C.x * w, py = C.y * w;          // correction C * w^(u+1)
        #pragma unroll
        for (int u = 0; u < CH; ++u) {
            float2 r;
            r.x = v[u].x + px;
            r.y = v[u].y + py;
            op[(size_t)(chunk_start + u) * (HS / 2)] = r;
            px *= w;
            py *= w;
        }
    }
}

extern "C" void kernel_launch(void* const* d_in, const int* in_sizes, int n_in,
                              void* d_out, int out_size)
{
    const float* k    = (const float*)d_in[0];   // (B, NH, T, HS) f32
    const float* beta = (const float*)d_in[1];   // (1, NH, 1, 1) f32
    float*       out  = (float*)d_out;           // (B, NH, T, HS) f32

    const int blocks = NROWS * NTILES;           // 1024
    leaky_avg_kernel<<<blocks, THREADS>>>(k, beta, out);
}